// round 7
// baseline (speedup 1.0000x reference)
#include <cuda_runtime.h>
#include <cstdint>

#define N_NODES 100000
#define N_EDGES 3200000
#define E4 (N_EDGES / 4)
#define N2 (N_NODES / 2)

// Scratch (device globals — no allocation allowed)
__device__ float  g_deg[N_NODES];    // raw in-degree (no self-loop); memset to 0
__device__ float  g_dinv[N_NODES];
__device__ float2 g_xs[N_NODES];     // x[i] * dinv[i]
__device__ float2 g_agg1[N_NODES];
__device__ float2 g_ps[N_NODES];     // (h1@W2)[i] * dinv[i]
__device__ float2 g_agg2[N_NODES];

__device__ __forceinline__ void red_add_f2(float2* addr, float2 v) {
    asm volatile("red.global.add.v2.f32 [%0], {%1, %2};"
                 :: "l"(addr), "f"(v.x), "f"(v.y) : "memory");
}
__device__ __forceinline__ void red_add_f(float* addr, float v) {
    asm volatile("red.global.add.f32 [%0], %1;"
                 :: "l"(addr), "f"(v) : "memory");
}

// ---------------------------------------------------------------------------
__global__ void k_degree(const int4* __restrict__ dst4) {
    int t = blockIdx.x * blockDim.x + threadIdx.x;
    if (t < E4) {
        int4 d = dst4[t];
        red_add_f(&g_deg[d.x], 1.0f);
        red_add_f(&g_deg[d.y], 1.0f);
        red_add_f(&g_deg[d.z], 1.0f);
        red_add_f(&g_deg[d.w], 1.0f);
    }
}

// 2 nodes per thread, float4 vector I/O.
__global__ void k_pre1(const float4* __restrict__ x4) {
    int t = blockIdx.x * blockDim.x + threadIdx.x;
    if (t >= N2) return;
    int i = 2 * t;
    float2 dg = *(const float2*)&g_deg[i];
    float d0 = rsqrtf(dg.x + 1.0f);
    float d1 = rsqrtf(dg.y + 1.0f);
    *(float2*)&g_dinv[i] = make_float2(d0, d1);
    float4 xi = x4[t];                      // nodes i, i+1
    float4 xs = make_float4(xi.x * d0, xi.y * d0, xi.z * d1, xi.w * d1);
    *(float4*)&g_xs[i]   = xs;
    *(float4*)&g_agg1[i] = xs;              // self-loop seed
}

__global__ void k_scatter1(const int4* __restrict__ src4,
                           const int4* __restrict__ dst4) {
    int t = blockIdx.x * blockDim.x + threadIdx.x;
    if (t < E4) {
        int4 s = src4[t];
        int4 d = dst4[t];
        float2 v0 = g_xs[s.x];
        float2 v1 = g_xs[s.y];
        float2 v2 = g_xs[s.z];
        float2 v3 = g_xs[s.w];
        red_add_f2(&g_agg1[d.x], v0);
        red_add_f2(&g_agg1[d.y], v1);
        red_add_f2(&g_agg1[d.z], v2);
        red_add_f2(&g_agg1[d.w], v3);
    }
}

// 2 nodes per thread; W1/b1/W2 hoisted to registers.
__global__ void k_mid(const float* __restrict__ W1,   // [2,16]
                      const float* __restrict__ b1,   // [16]
                      const float* __restrict__ W2) { // [16,2]
    int t = blockIdx.x * blockDim.x + threadIdx.x;
    if (t >= N2) return;
    int i = 2 * t;

    float w1a[16], w1b[16], bb[16], w2x[16], w2y[16];
#pragma unroll
    for (int j = 0; j < 16; j++) {
        w1a[j] = __ldg(&W1[j]);
        w1b[j] = __ldg(&W1[16 + j]);
        bb[j]  = __ldg(&b1[j]);
        w2x[j] = __ldg(&W2[2 * j]);
        w2y[j] = __ldg(&W2[2 * j + 1]);
    }

    float2 dv = *(const float2*)&g_dinv[i];
    float4 tt = *(const float4*)&g_agg1[i];
    float a0x = tt.x * dv.x, a0y = tt.y * dv.x;
    float a1x = tt.z * dv.y, a1y = tt.w * dv.y;

    float p0x = 0.f, p0y = 0.f, p1x = 0.f, p1y = 0.f;
#pragma unroll
    for (int j = 0; j < 16; j++) {
        float h0 = fmaxf(a0x * w1a[j] + a0y * w1b[j] + bb[j], 0.f);
        float h1 = fmaxf(a1x * w1a[j] + a1y * w1b[j] + bb[j], 0.f);
        p0x += h0 * w2x[j];  p0y += h0 * w2y[j];
        p1x += h1 * w2x[j];  p1y += h1 * w2y[j];
    }
    float4 ps = make_float4(p0x * dv.x, p0y * dv.x, p1x * dv.y, p1y * dv.y);
    *(float4*)&g_ps[i]   = ps;
    *(float4*)&g_agg2[i] = ps;              // self-loop seed
}

__global__ void k_scatter2(const int4* __restrict__ src4,
                           const int4* __restrict__ dst4) {
    int t = blockIdx.x * blockDim.x + threadIdx.x;
    if (t < E4) {
        int4 s = src4[t];
        int4 d = dst4[t];
        float2 v0 = g_ps[s.x];
        float2 v1 = g_ps[s.y];
        float2 v2 = g_ps[s.z];
        float2 v3 = g_ps[s.w];
        red_add_f2(&g_agg2[d.x], v0);
        red_add_f2(&g_agg2[d.y], v1);
        red_add_f2(&g_agg2[d.z], v2);
        red_add_f2(&g_agg2[d.w], v3);
    }
}

// 2 nodes per thread, fast-math log-softmax.
__global__ void k_out(const float* __restrict__ b2, float4* __restrict__ out4) {
    int t = blockIdx.x * blockDim.x + threadIdx.x;
    if (t >= N2) return;
    int i = 2 * t;
    float bx = __ldg(&b2[0]), by = __ldg(&b2[1]);
    float2 dv = *(const float2*)&g_dinv[i];
    float4 tt = *(const float4*)&g_agg2[i];
    float z0x = tt.x * dv.x + bx, z0y = tt.y * dv.x + by;
    float z1x = tt.z * dv.y + bx, z1y = tt.w * dv.y + by;

    float m0 = fmaxf(z0x, z0y);
    float l0 = m0 + __logf(__expf(z0x - m0) + __expf(z0y - m0));
    float m1 = fmaxf(z1x, z1y);
    float l1 = m1 + __logf(__expf(z1x - m1) + __expf(z1y - m1));
    out4[t] = make_float4(z0x - l0, z0y - l0, z1x - l1, z1y - l1);
}

// ---------------------------------------------------------------------------
extern "C" void kernel_launch(void* const* d_in, const int* in_sizes, int n_in,
                              void* d_out, int out_size) {
    const float* x  = (const float*)d_in[0];   // [N,2]
    const int*   ei = (const int*)d_in[1];     // [2,E] int32
    const float* W1 = (const float*)d_in[2];
    const float* b1 = (const float*)d_in[3];
    const float* W2 = (const float*)d_in[4];
    const float* b2 = (const float*)d_in[5];

    const int4* src4 = (const int4*)ei;
    const int4* dst4 = (const int4*)(ei + N_EDGES);
    const float4* x4 = (const float4*)x;
    float4* out4 = (float4*)d_out;

    const int T = 256;
    const int gN2 = (N2 + T - 1) / T;
    const int gE4 = (E4 + T - 1) / T;

    float* deg_addr = nullptr;
    cudaGetSymbolAddress((void**)&deg_addr, g_deg);
    cudaMemsetAsync(deg_addr, 0, N_NODES * sizeof(float));

    k_degree<<<gE4, T>>>(dst4);
    k_pre1<<<gN2, T>>>(x4);
    k_scatter1<<<gE4, T>>>(src4, dst4);
    k_mid<<<gN2, T>>>(W1, b1, W2);
    k_scatter2<<<gE4, T>>>(src4, dst4);
    k_out<<<gN2, T>>>(b2, out4);
}

// round 9
// speedup vs baseline: 1.0162x; 1.0162x over previous
#include <cuda_runtime.h>
#include <cstdint>

#define N_NODES 100000
#define N_EDGES 3200000
#define E4 (N_EDGES / 4)
#define N2 (N_NODES / 2)

// Scratch (device globals — zero-initialized at module load; no allocation).
// g_deg is consume-and-reset: k_degree accumulates, k_pre1 reads then zeroes,
// so every graph replay starts from 0 without a memset node.
__device__ float  g_deg[N_NODES];
__device__ float  g_dinv[N_NODES];
__device__ float2 g_xs[N_NODES];     // x[i] * dinv[i]
__device__ float2 g_agg1[N_NODES];
__device__ float2 g_ps[N_NODES];     // (h1@W2)[i] * dinv[i]
__device__ float2 g_agg2[N_NODES];

__device__ __forceinline__ void red_add_f2(float2* addr, float2 v) {
    asm volatile("red.global.add.v2.f32 [%0], {%1, %2};"
                 :: "l"(addr), "f"(v.x), "f"(v.y) : "memory");
}
__device__ __forceinline__ void red_add_f(float* addr, float v) {
    asm volatile("red.global.add.f32 [%0], %1;"
                 :: "l"(addr), "f"(v) : "memory");
}

// ---------------------------------------------------------------------------
__global__ void k_degree(const int4* __restrict__ dst4) {
    int t = blockIdx.x * blockDim.x + threadIdx.x;
    if (t < E4) {
        int4 d = dst4[t];
        red_add_f(&g_deg[d.x], 1.0f);
        red_add_f(&g_deg[d.y], 1.0f);
        red_add_f(&g_deg[d.z], 1.0f);
        red_add_f(&g_deg[d.w], 1.0f);
    }
}

// 2 nodes per thread, float4 vector I/O; resets g_deg for next replay.
__global__ void k_pre1(const float4* __restrict__ x4) {
    int t = blockIdx.x * blockDim.x + threadIdx.x;
    if (t >= N2) return;
    int i = 2 * t;
    float2 dg = *(const float2*)&g_deg[i];
    *(float2*)&g_deg[i] = make_float2(0.f, 0.f);   // consume-and-reset
    float d0 = rsqrtf(dg.x + 1.0f);                // +1 self-loop
    float d1 = rsqrtf(dg.y + 1.0f);
    *(float2*)&g_dinv[i] = make_float2(d0, d1);
    float4 xi = x4[t];                             // nodes i, i+1
    float4 xs = make_float4(xi.x * d0, xi.y * d0, xi.z * d1, xi.w * d1);
    *(float4*)&g_xs[i]   = xs;
    *(float4*)&g_agg1[i] = xs;                     // self-loop seed
}

__global__ void k_scatter1(const int4* __restrict__ src4,
                           const int4* __restrict__ dst4) {
    int t = blockIdx.x * blockDim.x + threadIdx.x;
    if (t < E4) {
        int4 s = src4[t];
        int4 d = dst4[t];
        float2 v0 = __ldg(&g_xs[s.x]);
        float2 v1 = __ldg(&g_xs[s.y]);
        float2 v2 = __ldg(&g_xs[s.z]);
        float2 v3 = __ldg(&g_xs[s.w]);
        red_add_f2(&g_agg1[d.x], v0);
        red_add_f2(&g_agg1[d.y], v1);
        red_add_f2(&g_agg1[d.z], v2);
        red_add_f2(&g_agg1[d.w], v3);
    }
}

// 2 nodes per thread; weights hoisted to registers.
__global__ void k_mid(const float* __restrict__ W1,   // [2,16]
                      const float* __restrict__ b1,   // [16]
                      const float* __restrict__ W2) { // [16,2]
    int t = blockIdx.x * blockDim.x + threadIdx.x;
    if (t >= N2) return;
    int i = 2 * t;

    float w1a[16], w1b[16], bb[16], w2x[16], w2y[16];
#pragma unroll
    for (int j = 0; j < 16; j++) {
        w1a[j] = __ldg(&W1[j]);
        w1b[j] = __ldg(&W1[16 + j]);
        bb[j]  = __ldg(&b1[j]);
        w2x[j] = __ldg(&W2[2 * j]);
        w2y[j] = __ldg(&W2[2 * j + 1]);
    }

    float2 dv = *(const float2*)&g_dinv[i];
    float4 tt = *(const float4*)&g_agg1[i];
    float a0x = tt.x * dv.x, a0y = tt.y * dv.x;
    float a1x = tt.z * dv.y, a1y = tt.w * dv.y;

    float p0x = 0.f, p0y = 0.f, p1x = 0.f, p1y = 0.f;
#pragma unroll
    for (int j = 0; j < 16; j++) {
        float h0 = fmaxf(a0x * w1a[j] + a0y * w1b[j] + bb[j], 0.f);
        float h1 = fmaxf(a1x * w1a[j] + a1y * w1b[j] + bb[j], 0.f);
        p0x += h0 * w2x[j];  p0y += h0 * w2y[j];
        p1x += h1 * w2x[j];  p1y += h1 * w2y[j];
    }
    float4 ps = make_float4(p0x * dv.x, p0y * dv.x, p1x * dv.y, p1y * dv.y);
    *(float4*)&g_ps[i]   = ps;
    *(float4*)&g_agg2[i] = ps;                     // self-loop seed
}

__global__ void k_scatter2(const int4* __restrict__ src4,
                           const int4* __restrict__ dst4) {
    int t = blockIdx.x * blockDim.x + threadIdx.x;
    if (t < E4) {
        int4 s = src4[t];
        int4 d = dst4[t];
        float2 v0 = __ldg(&g_ps[s.x]);
        float2 v1 = __ldg(&g_ps[s.y]);
        float2 v2 = __ldg(&g_ps[s.z]);
        float2 v3 = __ldg(&g_ps[s.w]);
        red_add_f2(&g_agg2[d.x], v0);
        red_add_f2(&g_agg2[d.y], v1);
        red_add_f2(&g_agg2[d.z], v2);
        red_add_f2(&g_agg2[d.w], v3);
    }
}

// 2 nodes per thread, fast-math log-softmax.
__global__ void k_out(const float* __restrict__ b2, float4* __restrict__ out4) {
    int t = blockIdx.x * blockDim.x + threadIdx.x;
    if (t >= N2) return;
    int i = 2 * t;
    float bx = __ldg(&b2[0]), by = __ldg(&b2[1]);
    float2 dv = *(const float2*)&g_dinv[i];
    float4 tt = *(const float4*)&g_agg2[i];
    float z0x = tt.x * dv.x + bx, z0y = tt.y * dv.x + by;
    float z1x = tt.z * dv.y + bx, z1y = tt.w * dv.y + by;

    float m0 = fmaxf(z0x, z0y);
    float l0 = m0 + __logf(__expf(z0x - m0) + __expf(z0y - m0));
    float m1 = fmaxf(z1x, z1y);
    float l1 = m1 + __logf(__expf(z1x - m1) + __expf(z1y - m1));
    out4[t] = make_float4(z0x - l0, z0y - l0, z1x - l1, z1y - l1);
}

// ---------------------------------------------------------------------------
extern "C" void kernel_launch(void* const* d_in, const int* in_sizes, int n_in,
                              void* d_out, int out_size) {
    const float* x  = (const float*)d_in[0];   // [N,2]
    const int*   ei = (const int*)d_in[1];     // [2,E] int32
    const float* W1 = (const float*)d_in[2];
    const float* b1 = (const float*)d_in[3];
    const float* W2 = (const float*)d_in[4];
    const float* b2 = (const float*)d_in[5];

    const int4* src4 = (const int4*)ei;
    const int4* dst4 = (const int4*)(ei + N_EDGES);
    const float4* x4 = (const float4*)x;
    float4* out4 = (float4*)d_out;

    const int TE = 256;                 // edge kernels
    const int TN = 128;                 // node kernels: more CTAs, less tail
    const int gN2 = (N2 + TN - 1) / TN;
    const int gE4 = (E4 + TE - 1) / TE;

    k_degree<<<gE4, TE>>>(dst4);
    k_pre1<<<gN2, TN>>>(x4);
    k_scatter1<<<gE4, TE>>>(src4, dst4);
    k_mid<<<gN2, TN>>>(W1, b1, W2);
    k_scatter2<<<gE4, TE>>>(src4, dst4);
    k_out<<<gN2, TN>>>(b2, out4);
}